// round 15
// baseline (speedup 1.0000x reference)
#include <cuda_runtime.h>
#include <cuda_bf16.h>
#include <cuda_fp8.h>
#include <cstdint>

// Problem dims
#define BQ 64
#define LQ 256
#define DQ 1024
#define FQ 1024
#define MQ (BQ * LQ)    // 16384 GEMM rows
#define NQ (2 * FQ)     // 2048 interleaved: col 2f = X@W0[:,f] ("a"), col 2f+1 = X@W1[:,f] ("c")

#define WSCALE 64.0f
#define ACC_SCALE 0.015625f   // 1/64, applied at epilogue (max-plus recurrence is degree-1 homogeneous)

// ---------------- scratch (device globals: no allocation allowed) ----------------
__device__ __align__(1024) uint8_t g_X8[MQ * DQ];         // X e4m3 [M, D]
__device__ __align__(1024) uint8_t g_Wt8[NQ * DQ];        // interleaved [W0^T|W1^T] e4m3*64 [2048, D]
// per-half-sequence recurrence summaries: index [m_tile 0..127][f 0..1023]
__device__ float g_pA[128 * FQ];
__device__ float g_pC[128 * FQ];
__device__ float g_pH[128 * FQ];

// ---------------- helpers ----------------
__device__ __forceinline__ uint32_t smem_u32(const void* p) {
    uint32_t a;
    asm("{ .reg .u64 t; cvta.to.shared.u64 t, %1; cvt.u32.u64 %0, t; }" : "=r"(a) : "l"(p));
    return a;
}

#define CP_ASYNC16(dst_u32, src_ptr) \
    asm volatile("cp.async.cg.shared.global [%0], [%1], 16;" :: "r"(dst_u32), "l"(src_ptr))
#define CP_COMMIT() asm volatile("cp.async.commit_group;" ::: "memory")

#define SW128(off) ((off) ^ (((off) >> 3) & 0x70))

__device__ __forceinline__ void ldsm_x4(uint32_t* r, uint32_t addr) {
    asm volatile("ldmatrix.sync.aligned.m8n8.x4.shared.b16 {%0,%1,%2,%3}, [%4];"
                 : "=r"(r[0]), "=r"(r[1]), "=r"(r[2]), "=r"(r[3]) : "r"(addr));
}

// fp8 e4m3 MMA, k32 — fragment byte-layout identical to bf16 k16 fragments
__device__ __forceinline__ void mma16832_fp8(float* d, const uint32_t* a, const uint32_t* b) {
    asm volatile(
        "mma.sync.aligned.m16n8k32.row.col.f32.e4m3.e4m3.f32 "
        "{%0,%1,%2,%3}, {%4,%5,%6,%7}, {%8,%9}, {%0,%1,%2,%3};"
        : "+f"(d[0]), "+f"(d[1]), "+f"(d[2]), "+f"(d[3])
        : "r"(a[0]), "r"(a[1]), "r"(a[2]), "r"(a[3]), "r"(b[0]), "r"(b[1]));
}

// ---------------- GEMM config (R8 structure; fp8 doubles K per stage) ----------------
#define TM 128                       // half a sequence per CTA
#define TN 64                        // 32 interleaved (a,c) column pairs
#define KC 128                       // fp8 elems per K stage -> 128 B rows (SW128, conflict-free)
#define NK (DQ / KC)                 // 8
#define A_ST (TM * 128)              // 16 KB
#define B_ST (TN * 128)              // 8 KB
#define STB (A_ST + B_ST)            // 24 KB
#define NSTG 2
#define SMEM_BYTES (NSTG * STB)      // 48 KB -> 4 CTAs/SM (192 KB)
// epilogue reuses pipeline smem: uint32 (bf16x2) scanb[128][33] = 16.9 KB
#define SCAN_STRIDE 33
#define SEGBUF_OFF (20 * 1024)       // 3 x 128 floats = 1.5 KB, ends < 22 KB << 48 KB

#define NTHREADS 128                 // 4 warps, warp tile 64x32, 4 CTAs/SM

// ---------------- merged prep: X->e4m3 (ILP=2) + W transpose->e4m3*64 ----------------
#define XHALF (MQ * DQ / 8)          // float4s per half-stream = 2097152
__device__ __forceinline__ uint32_t pack_fp8x4(float a, float b, float c, float d) {
    __nv_fp8x2_storage_t lo = __nv_cvt_float2_to_fp8x2(make_float2(a, b), __NV_SATFINITE, __NV_E4M3);
    __nv_fp8x2_storage_t hi = __nv_cvt_float2_to_fp8x2(make_float2(c, d), __NV_SATFINITE, __NV_E4M3);
    return (uint32_t)lo | ((uint32_t)hi << 16);
}

__global__ void prep_kernel(const float4* __restrict__ x,
                            const float* __restrict__ W0, const float* __restrict__ W1) {
    __shared__ float t[32][33];
    int bid = blockIdx.x;
    int tid = threadIdx.x;
    if (bid < XHALF / 256) {
        // --- X fp32 -> e4m3, 2 independent float4 per thread (MLP=2) ---
        int i = bid * 256 + tid;
        float4 v0 = x[i];
        float4 v1 = x[i + XHALF];
        uint32_t* out = reinterpret_cast<uint32_t*>(g_X8);
        out[i]         = pack_fp8x4(v0.x, v0.y, v0.z, v0.w);
        out[i + XHALF] = pack_fp8x4(v1.x, v1.y, v1.z, v1.w);
    } else {
        // --- W[d,f] fp32 -> g_Wt8[2f+z][d] e4m3 of (w*64) ---
        int wb = bid - XHALF / 256;                // 0..2047
        int z  = wb >> 10;                         // W0 / W1
        int f0 = ((wb >> 5) & 31) * 32;
        int d0 = (wb & 31) * 32;
        int tx = tid & 31, ty = tid >> 5;          // 32 x 8
        const float* W = z ? W1 : W0;
#pragma unroll
        for (int r = 0; r < 4; r++)
            t[ty + 8 * r][tx] = W[(size_t)(d0 + ty + 8 * r) * FQ + f0 + tx];
        __syncthreads();
#pragma unroll
        for (int r = 0; r < 4; r++)
            g_Wt8[(size_t)(2 * (f0 + ty + 8 * r) + z) * DQ + d0 + tx] =
                (uint8_t)__nv_cvt_float_to_fp8(t[tx][ty + 8 * r] * WSCALE,
                                               __NV_SATFINITE, __NV_E4M3);
    }
}

// pad: keeps the fused GEMM as launch #4 overall (empirical ncu capture target).
__global__ void pad_kernel() {}

// ---------------- fused dual GEMM (fp8) + partial recurrence ----------------
__device__ __forceinline__ void load_stage(uint32_t stage_base, const uint8_t* xg,
                                           const uint8_t* wg, int kc, int tid) {
    const uint8_t* xs = xg + kc * KC;   // KC bytes per stage
    const uint8_t* ws = wg + kc * KC;
    // A: 128 rows x 8 chunks of 16B = 1024 -> 8 per thread
#pragma unroll
    for (int i = 0; i < 8; i++) {
        int c = i * NTHREADS + tid;
        int r = c >> 3, j = c & 7;
        uint32_t off = (uint32_t)(r * 128 + j * 16);
        CP_ASYNC16(stage_base + SW128(off), xs + (size_t)r * DQ + j * 16);
    }
    // B: 64 rows x 8 chunks = 512 -> 4 per thread
#pragma unroll
    for (int i = 0; i < 4; i++) {
        int c = i * NTHREADS + tid;
        int r = c >> 3, j = c & 7;
        uint32_t off = (uint32_t)(r * 128 + j * 16);
        CP_ASYNC16(stage_base + A_ST + SW128(off), ws + (size_t)r * DQ + j * 16);
    }
    CP_COMMIT();
}

__global__ void __launch_bounds__(NTHREADS, 4)
fused_gemm_scan_kernel() {
    extern __shared__ char smem[];
    uint32_t sbase = smem_u32(smem);
    int tid = threadIdx.x;
    int wid = tid >> 5, lane = tid & 31;
    int warp_m = wid & 1;     // 2 -> 64 rows each
    int warp_n = wid >> 1;    // 2 -> 32 cols each
    const int mt = blockIdx.x;            // m-tile 0..127 (batch b = mt>>1, half = mt&1)
    const int n0 = blockIdx.y * TN;       // interleaved col tile

    const uint8_t* xg = g_X8  + (size_t)(mt * TM) * DQ;
    const uint8_t* wg = g_Wt8 + (size_t)n0 * DQ;

    float acc[4][4][4];
#pragma unroll
    for (int mi = 0; mi < 4; mi++)
#pragma unroll
        for (int ni = 0; ni < 4; ni++)
#pragma unroll
            for (int e = 0; e < 4; e++) acc[mi][ni][e] = 0.f;

    load_stage(sbase, xg, wg, 0, tid);

    int lr = lane & 15;       // ldmatrix row-within-16
    int lc = lane >> 4;       // 16B column-half select

    for (int kc = 0; kc < NK; kc++) {
        asm volatile("cp.async.wait_group 0;" ::: "memory");
        __syncthreads();      // stage kc resident + all warps done with prior buffer

        if (kc + 1 < NK)
            load_stage(sbase + ((kc + 1) & 1) * STB, xg, wg, kc + 1, tid);   // overlaps compute

        uint32_t sa = sbase + (kc & 1) * STB;
        uint32_t sb = sa + A_ST;

#pragma unroll
        for (int k32 = 0; k32 < 4; k32++) {        // 4 x 32B k-chunks per 128B row
            uint32_t av[4][4];
#pragma unroll
            for (int mi = 0; mi < 4; mi++) {
                int r = warp_m * 64 + mi * 16 + lr;
                uint32_t off = (uint32_t)(r * 128 + (k32 * 2 + lc) * 16);
                ldsm_x4(av[mi], sa + SW128(off));
            }
            uint32_t bv[2][4];
#pragma unroll
            for (int p = 0; p < 2; p++) {
                int r = warp_n * 32 + p * 16 + lr;
                uint32_t off = (uint32_t)(r * 128 + (k32 * 2 + lc) * 16);
                ldsm_x4(bv[p], sb + SW128(off));
            }
#pragma unroll
            for (int mi = 0; mi < 4; mi++) {
#pragma unroll
                for (int ni = 0; ni < 4; ni++) {
                    uint32_t b2[2] = { bv[ni >> 1][ni & 1], bv[ni >> 1][2 + (ni & 1)] };
                    mma16832_fp8(acc[mi][ni], av[mi], b2);
                }
            }
        }
    }

    // ---------- epilogue: descale (1/64), per-half-sequence (A, C, H) summary ----------
    // acc col: c0 = warp_n*32 + ni*8 + (lane&3)*2 -> pair f = warp_n*16 + ni*4 + (lane&3)
    __syncthreads();   // mainloop fully done before smem reuse
    uint32_t* scanb = reinterpret_cast<uint32_t*>(smem);   // [128][SCAN_STRIDE] bf16x2(a,c)
#pragma unroll
    for (int mi = 0; mi < 4; mi++) {
        int r0 = warp_m * 64 + mi * 16 + (lane >> 2);
#pragma unroll
        for (int ni = 0; ni < 4; ni++) {
            int f = warp_n * 16 + ni * 4 + (lane & 3);
            __nv_bfloat162 h0, h1;
            h0.x = __float2bfloat16(acc[mi][ni][0] * ACC_SCALE);   // a at row r0
            h0.y = __float2bfloat16(acc[mi][ni][1] * ACC_SCALE);   // c at row r0
            h1.x = __float2bfloat16(acc[mi][ni][2] * ACC_SCALE);   // a at row r0+8
            h1.y = __float2bfloat16(acc[mi][ni][3] * ACC_SCALE);   // c at row r0+8
            scanb[r0 * SCAN_STRIDE + f]       = *reinterpret_cast<uint32_t*>(&h0);
            scanb[(r0 + 8) * SCAN_STRIDE + f] = *reinterpret_cast<uint32_t*>(&h1);
        }
    }
    __syncthreads();

    // per-segment summaries: 128 threads = 32 f x 4 segments of 32 steps
    float* segA = reinterpret_cast<float*>(smem + SEGBUF_OFF);
    float* segC = segA + 128;
    float* segH = segC + 128;
    {
        int f = tid & 31, s = tid >> 5;
        float P = -1e30f, C = -1e30f, H = -1e30f;
        const uint32_t* col = scanb + (size_t)(s * 32) * SCAN_STRIDE + f;
#pragma unroll 4
        for (int l = 0; l < 32; l++) {
            uint32_t u = col[l * SCAN_STRIDE];
            __nv_bfloat162 v = *reinterpret_cast<__nv_bfloat162*>(&u);
            float a = __bfloat162float(v.x), c = __bfloat162float(v.y);
            H = fmaxf(H, P + c);   // prefix (strictly before t) within segment
            C = fmaxf(C, c);
            P = fmaxf(P, a);
        }
        segA[s * 32 + f] = P;
        segC[s * 32 + f] = C;
        segH[s * 32 + f] = H;
    }
    __syncthreads();

    // fold 4 segments into one (A, C, H) triple per f, write to global partials
    if (tid < 32) {
        float Aa = -1e30f, Cc = -1e30f, Hh = -1e30f;
#pragma unroll
        for (int s = 0; s < 4; s++) {
            Hh = fmaxf(fmaxf(Hh, segH[s * 32 + tid]), Aa + segC[s * 32 + tid]);
            Cc = fmaxf(Cc, segC[s * 32 + tid]);
            Aa = fmaxf(Aa, segA[s * 32 + tid]);
        }
        int fg = blockIdx.y * 32 + tid;
        g_pA[mt * FQ + fg] = Aa;
        g_pC[mt * FQ + fg] = Cc;
        g_pH[mt * FQ + fg] = Hh;
    }
}

// ---------------- combine halves + tanh ----------------
__global__ void combine_kernel(const float* __restrict__ bias, float* __restrict__ out) {
    int idx = blockIdx.x * blockDim.x + threadIdx.x;   // 65536
    int b = idx >> 10, f = idx & 1023;
    int x0 = (2 * b) * FQ + f, x1 = (2 * b + 1) * FQ + f;
    float A0 = g_pA[x0], C0 = g_pC[x0], H0 = g_pH[x0];
    float C1 = g_pC[x1], H1 = g_pH[x1];
    // concat halves: H = max(H0, H1, A0 + C1); C = max(C0, C1)
    float H = fmaxf(fmaxf(H0, H1), A0 + C1);
    float C = fmaxf(C0, C1);
    // apply h1=0, h2=0 inits: h2_final = max(0, C, H)
    float res = fmaxf(0.f, fmaxf(C, H));
    out[idx] = tanhf(res + bias[f]);
}

// ---------------- launch ----------------
extern "C" void kernel_launch(void* const* d_in, const int* in_sizes, int n_in,
                              void* d_out, int out_size) {
    const float* x    = (const float*)d_in[0];   // [64, 256, 1024]
    const float* W0   = (const float*)d_in[1];   // [1024, 1024]
    const float* W1   = (const float*)d_in[2];   // [1024, 1024]
    const float* bias = (const float*)d_in[3];   // [1024]
    float* out        = (float*)d_out;           // [64, 1024]

    cudaFuncSetAttribute(fused_gemm_scan_kernel,
                         cudaFuncAttributeMaxDynamicSharedMemorySize, SMEM_BYTES);

    // GEMM kept as launch #4 (empirical ncu capture target).
    // 1) merged prep: X->e4m3 (ILP=2) + W transpose->e4m3*64, concurrent blocks
    prep_kernel<<<XHALF / 256 + 2048, 256>>>(
        reinterpret_cast<const float4*>(x), W0, W1);
    // 2-3) alignment pads (no-op)
    pad_kernel<<<1, 32>>>();
    pad_kernel<<<1, 32>>>();
    // 4) fused dual GEMM (fp8 QMMA) + partial recurrence (4 CTAs/SM, grid 4096)
    fused_gemm_scan_kernel<<<dim3(MQ / TM, NQ / TN), NTHREADS, SMEM_BYTES>>>();
    // 5) combine halves + tanh
    combine_kernel<<<(BQ * FQ) / 256, 256>>>(bias, out);
}

// round 16
// speedup vs baseline: 1.0850x; 1.0850x over previous
#include <cuda_runtime.h>
#include <cuda_bf16.h>
#include <cstdint>

// Problem dims
#define BQ 64
#define LQ 256
#define DQ 1024
#define FQ 1024
#define MQ (BQ * LQ)    // 16384 GEMM rows
#define NQ (2 * FQ)     // 2048 interleaved: col 2f = X@W0[:,f] ("a"), col 2f+1 = X@W1[:,f] ("c")

// ---------------- scratch (device globals: no allocation allowed) ----------------
__device__ __align__(1024) __nv_bfloat16 g_Xb[MQ * DQ];   // X bf16 [M, D]
__device__ __align__(1024) __nv_bfloat16 g_Wt[NQ * DQ];   // interleaved [W0^T|W1^T] bf16 [2048, D]
// per-half-sequence recurrence summaries: index [m_tile 0..127][f 0..1023]
__device__ float g_pA[128 * FQ];
__device__ float g_pC[128 * FQ];
__device__ float g_pH[128 * FQ];

// ---------------- helpers ----------------
__device__ __forceinline__ uint32_t smem_u32(const void* p) {
    uint32_t a;
    asm("{ .reg .u64 t; cvta.to.shared.u64 t, %1; cvt.u32.u64 %0, t; }" : "=r"(a) : "l"(p));
    return a;
}

#define CP_ASYNC16(dst_u32, src_ptr) \
    asm volatile("cp.async.cg.shared.global [%0], [%1], 16;" :: "r"(dst_u32), "l"(src_ptr))
#define CP_COMMIT() asm volatile("cp.async.commit_group;" ::: "memory")

#define SW128(off) ((off) ^ (((off) >> 3) & 0x70))

__device__ __forceinline__ void ldsm_x4(uint32_t* r, uint32_t addr) {
    asm volatile("ldmatrix.sync.aligned.m8n8.x4.shared.b16 {%0,%1,%2,%3}, [%4];"
                 : "=r"(r[0]), "=r"(r[1]), "=r"(r[2]), "=r"(r[3]) : "r"(addr));
}

__device__ __forceinline__ void mma16816(float* d, const uint32_t* a, const uint32_t* b) {
    asm volatile(
        "mma.sync.aligned.m16n8k16.row.col.f32.bf16.bf16.f32 "
        "{%0,%1,%2,%3}, {%4,%5,%6,%7}, {%8,%9}, {%0,%1,%2,%3};"
        : "+f"(d[0]), "+f"(d[1]), "+f"(d[2]), "+f"(d[3])
        : "r"(a[0]), "r"(a[1]), "r"(a[2]), "r"(a[3]), "r"(b[0]), "r"(b[1]));
}

// ---------------- GEMM config (R8 proven optimum — frozen) ----------------
#define TM 128                       // half a sequence per CTA
#define TN 64                        // 32 interleaved (a,c) column pairs
#define KC 64                        // bf16 elems per K stage -> 128 B rows (SW128, conflict-free)
#define NK (DQ / KC)                 // 16
#define A_ST (TM * 128)              // 16 KB
#define B_ST (TN * 128)              // 8 KB
#define STB (A_ST + B_ST)            // 24 KB
#define NSTG 2
#define SMEM_BYTES (NSTG * STB)      // 48 KB -> 4 CTAs/SM (192 KB)
// epilogue reuses pipeline smem: uint32 (bf16x2) scanb[128][33] = 16.9 KB
#define SCAN_STRIDE 33
#define SEGBUF_OFF (20 * 1024)       // 3 x 128 floats = 1.5 KB, ends < 22 KB << 48 KB

#define NTHREADS 128                 // 4 warps, warp tile 64x32, 4 CTAs/SM

// ---------------- merged prep: X convert (ILP=2) + W transpose (R11 proven) ----------------
#define XHALF (MQ * DQ / 8)          // float4s per half-stream = 2097152
__global__ void prep_kernel(const float4* __restrict__ x,
                            const float* __restrict__ W0, const float* __restrict__ W1) {
    __shared__ float t[32][33];
    int bid = blockIdx.x;
    int tid = threadIdx.x;
    if (bid < XHALF / 256) {
        // --- X fp32 -> bf16, 2 independent float4 per thread (MLP=2) ---
        int i = bid * 256 + tid;
        float4 v0 = x[i];
        float4 v1 = x[i + XHALF];
        __nv_bfloat162* out = reinterpret_cast<__nv_bfloat162*>(g_Xb);
        __nv_bfloat162 h;
        h.x = __float2bfloat16(v0.x); h.y = __float2bfloat16(v0.y); out[2 * i] = h;
        h.x = __float2bfloat16(v0.z); h.y = __float2bfloat16(v0.w); out[2 * i + 1] = h;
        h.x = __float2bfloat16(v1.x); h.y = __float2bfloat16(v1.y); out[2 * (i + XHALF)] = h;
        h.x = __float2bfloat16(v1.z); h.y = __float2bfloat16(v1.w); out[2 * (i + XHALF) + 1] = h;
    } else {
        // --- W[d,f] fp32 -> g_Wt[2f+z][d] bf16 (interleaved a/c rows) ---
        int wb = bid - XHALF / 256;                // 0..2047
        int z  = wb >> 10;                         // W0 / W1
        int f0 = ((wb >> 5) & 31) * 32;
        int d0 = (wb & 31) * 32;
        int tx = tid & 31, ty = tid >> 5;          // 32 x 8
        const float* W = z ? W1 : W0;
#pragma unroll
        for (int r = 0; r < 4; r++)
            t[ty + 8 * r][tx] = W[(size_t)(d0 + ty + 8 * r) * FQ + f0 + tx];
        __syncthreads();
#pragma unroll
        for (int r = 0; r < 4; r++)
            g_Wt[(size_t)(2 * (f0 + ty + 8 * r) + z) * DQ + d0 + tx] =
                __float2bfloat16(t[tx][ty + 8 * r]);
    }
}

// ---------------- fused dual GEMM + partial recurrence (R8 verbatim) ----------------
__device__ __forceinline__ void load_stage(uint32_t stage_base, const __nv_bfloat16* xg,
                                           const __nv_bfloat16* wg, int kc, int tid) {
    const __nv_bfloat16* xs = xg + kc * KC;
    const __nv_bfloat16* ws = wg + kc * KC;
    // A: 128 rows x 8 chunks of 16B = 1024 -> 8 per thread
#pragma unroll
    for (int i = 0; i < 8; i++) {
        int c = i * NTHREADS + tid;
        int r = c >> 3, j = c & 7;
        uint32_t off = (uint32_t)(r * 128 + j * 16);
        CP_ASYNC16(stage_base + SW128(off), xs + (size_t)r * DQ + j * 8);
    }
    // B: 64 rows x 8 chunks = 512 -> 4 per thread
#pragma unroll
    for (int i = 0; i < 4; i++) {
        int c = i * NTHREADS + tid;
        int r = c >> 3, j = c & 7;
        uint32_t off = (uint32_t)(r * 128 + j * 16);
        CP_ASYNC16(stage_base + A_ST + SW128(off), ws + (size_t)r * DQ + j * 8);
    }
    CP_COMMIT();
}

__global__ void __launch_bounds__(NTHREADS, 4)
fused_gemm_scan_kernel() {
    extern __shared__ char smem[];
    uint32_t sbase = smem_u32(smem);
    int tid = threadIdx.x;
    int wid = tid >> 5, lane = tid & 31;
    int warp_m = wid & 1;     // 2 -> 64 rows each
    int warp_n = wid >> 1;    // 2 -> 32 cols each
    const int mt = blockIdx.x;            // m-tile 0..127 (batch b = mt>>1, half = mt&1)
    const int n0 = blockIdx.y * TN;       // interleaved col tile

    const __nv_bfloat16* xg = g_Xb + (size_t)(mt * TM) * DQ;
    const __nv_bfloat16* wg = g_Wt + (size_t)n0 * DQ;

    float acc[4][4][4];
#pragma unroll
    for (int mi = 0; mi < 4; mi++)
#pragma unroll
        for (int ni = 0; ni < 4; ni++)
#pragma unroll
            for (int e = 0; e < 4; e++) acc[mi][ni][e] = 0.f;

    load_stage(sbase, xg, wg, 0, tid);

    int lr = lane & 15;       // ldmatrix row-within-16
    int lc = lane >> 4;       // 16B column-half select

    for (int kc = 0; kc < NK; kc++) {
        asm volatile("cp.async.wait_group 0;" ::: "memory");
        __syncthreads();      // stage kc resident + all warps done with prior buffer

        if (kc + 1 < NK)
            load_stage(sbase + ((kc + 1) & 1) * STB, xg, wg, kc + 1, tid);   // overlaps compute

        uint32_t sa = sbase + (kc & 1) * STB;
        uint32_t sb = sa + A_ST;

#pragma unroll
        for (int k16 = 0; k16 < 4; k16++) {
            uint32_t av[4][4];
#pragma unroll
            for (int mi = 0; mi < 4; mi++) {
                int r = warp_m * 64 + mi * 16 + lr;
                uint32_t off = (uint32_t)(r * 128 + (k16 * 2 + lc) * 16);
                ldsm_x4(av[mi], sa + SW128(off));
            }
            uint32_t bv[2][4];
#pragma unroll
            for (int p = 0; p < 2; p++) {
                int r = warp_n * 32 + p * 16 + lr;
                uint32_t off = (uint32_t)(r * 128 + (k16 * 2 + lc) * 16);
                ldsm_x4(bv[p], sb + SW128(off));
            }
#pragma unroll
            for (int mi = 0; mi < 4; mi++) {
#pragma unroll
                for (int ni = 0; ni < 4; ni++) {
                    uint32_t b2[2] = { bv[ni >> 1][ni & 1], bv[ni >> 1][2 + (ni & 1)] };
                    mma16816(acc[mi][ni], av[mi], b2);
                }
            }
        }
    }

    // ---------- epilogue: per-half-sequence (A, C, H) monoid summary ----------
    // acc col: c0 = warp_n*32 + ni*8 + (lane&3)*2 -> pair f = warp_n*16 + ni*4 + (lane&3)
    __syncthreads();   // mainloop fully done before smem reuse
    uint32_t* scanb = reinterpret_cast<uint32_t*>(smem);   // [128][SCAN_STRIDE] bf16x2(a,c)
#pragma unroll
    for (int mi = 0; mi < 4; mi++) {
        int r0 = warp_m * 64 + mi * 16 + (lane >> 2);
#pragma unroll
        for (int ni = 0; ni < 4; ni++) {
            int f = warp_n * 16 + ni * 4 + (lane & 3);
            __nv_bfloat162 h0, h1;
            h0.x = __float2bfloat16(acc[mi][ni][0]);   // a at row r0
            h0.y = __float2bfloat16(acc[mi][ni][1]);   // c at row r0
            h1.x = __float2bfloat16(acc[mi][ni][2]);   // a at row r0+8
            h1.y = __float2bfloat16(acc[mi][ni][3]);   // c at row r0+8
            scanb[r0 * SCAN_STRIDE + f]       = *reinterpret_cast<uint32_t*>(&h0);
            scanb[(r0 + 8) * SCAN_STRIDE + f] = *reinterpret_cast<uint32_t*>(&h1);
        }
    }
    __syncthreads();

    // per-segment summaries: 128 threads = 32 f x 4 segments of 32 steps
    float* segA = reinterpret_cast<float*>(smem + SEGBUF_OFF);
    float* segC = segA + 128;
    float* segH = segC + 128;
    {
        int f = tid & 31, s = tid >> 5;
        float P = -1e30f, C = -1e30f, H = -1e30f;
        const uint32_t* col = scanb + (size_t)(s * 32) * SCAN_STRIDE + f;
#pragma unroll 4
        for (int l = 0; l < 32; l++) {
            uint32_t u = col[l * SCAN_STRIDE];
            __nv_bfloat162 v = *reinterpret_cast<__nv_bfloat162*>(&u);
            float a = __bfloat162float(v.x), c = __bfloat162float(v.y);
            H = fmaxf(H, P + c);   // prefix (strictly before t) within segment
            C = fmaxf(C, c);
            P = fmaxf(P, a);
        }
        segA[s * 32 + f] = P;
        segC[s * 32 + f] = C;
        segH[s * 32 + f] = H;
    }
    __syncthreads();

    // fold 4 segments into one (A, C, H) triple per f, write to global partials
    if (tid < 32) {
        float Aa = -1e30f, Cc = -1e30f, Hh = -1e30f;
#pragma unroll
        for (int s = 0; s < 4; s++) {
            Hh = fmaxf(fmaxf(Hh, segH[s * 32 + tid]), Aa + segC[s * 32 + tid]);
            Cc = fmaxf(Cc, segC[s * 32 + tid]);
            Aa = fmaxf(Aa, segA[s * 32 + tid]);
        }
        int fg = blockIdx.y * 32 + tid;
        g_pA[mt * FQ + fg] = Aa;
        g_pC[mt * FQ + fg] = Cc;
        g_pH[mt * FQ + fg] = Hh;
    }
}

// ---------------- combine halves + tanh ----------------
__global__ void combine_kernel(const float* __restrict__ bias, float* __restrict__ out) {
    int idx = blockIdx.x * blockDim.x + threadIdx.x;   // 65536
    int b = idx >> 10, f = idx & 1023;
    int x0 = (2 * b) * FQ + f, x1 = (2 * b + 1) * FQ + f;
    float A0 = g_pA[x0], C0 = g_pC[x0], H0 = g_pH[x0];
    float C1 = g_pC[x1], H1 = g_pH[x1];
    // concat halves: H = max(H0, H1, A0 + C1); C = max(C0, C1)
    float H = fmaxf(fmaxf(H0, H1), A0 + C1);
    float C = fmaxf(C0, C1);
    // apply h1=0, h2=0 inits: h2_final = max(0, C, H)
    float res = fmaxf(0.f, fmaxf(C, H));
    out[idx] = tanhf(res + bias[f]);
}

// ---------------- launch ----------------
extern "C" void kernel_launch(void* const* d_in, const int* in_sizes, int n_in,
                              void* d_out, int out_size) {
    const float* x    = (const float*)d_in[0];   // [64, 256, 1024]
    const float* W0   = (const float*)d_in[1];   // [1024, 1024]
    const float* W1   = (const float*)d_in[2];   // [1024, 1024]
    const float* bias = (const float*)d_in[3];   // [1024]
    float* out        = (float*)d_out;           // [64, 1024]

    cudaFuncSetAttribute(fused_gemm_scan_kernel,
                         cudaFuncAttributeMaxDynamicSharedMemorySize, SMEM_BYTES);

    // 3 launches only — pad kernels removed (each cost ~3-4 us of launch overhead;
    // their ncu-capture-positioning job is done, the GEMM is characterized).
    // 1) merged prep: X->bf16 (ILP=2) + W transpose, concurrent blocks
    prep_kernel<<<XHALF / 256 + 2048, 256>>>(
        reinterpret_cast<const float4*>(x), W0, W1);
    // 2) fused dual GEMM + partial recurrence (R8 verbatim: 4 CTAs/SM, grid 4096)
    fused_gemm_scan_kernel<<<dim3(MQ / TM, NQ / TN), NTHREADS, SMEM_BYTES>>>();
    // 3) combine halves + tanh
    combine_kernel<<<(BQ * FQ) / 256, 256>>>(bias, out);
}